// round 7
// baseline (speedup 1.0000x reference)
#include <cuda_runtime.h>

// ---------------------------------------------------------------------------
// Graph_drug: 2-stack GraphSAGE (sum aggr) + global mean pool + concat
//   mol:    N=200000, E=1e6,  dims 78 -> 156 -> 312 -> 128
//   clique: N=120000, E=5e5,  dims 92 -> 184 -> 368 -> 128
//   G=4096 graphs, out [G, 256] fp32
// fp32 SIMT GEMM, 128x128x8 tiles, 8x8 register tile per thread.
// Global tile loads use float2 (all Din are even; Din=78 breaks float4 align).
// Layer 3 is transform-first (scatter at 128).
// ---------------------------------------------------------------------------

#define GRAPHS 4096
#define SCRATCH_ELEMS 62500000
__device__ float g_bufA[SCRATCH_ELEMS];
__device__ float g_bufB[SCRATCH_ELEMS];
__device__ float g_agg [SCRATCH_ELEMS];
__device__ int   g_cnt [2 * GRAPHS];

// ---------------------------------------------------------------------------
// Edge scatter: agg[dst] += x[src].  One warp per edge; float2 lanes.
__global__ void scatter_add(const float* __restrict__ x,
                            const int* __restrict__ ei,
                            int E, int D2,          // D2 = D/2
                            float* __restrict__ agg) {
    int w = (blockIdx.x * blockDim.x + threadIdx.x) >> 5;
    int lane = threadIdx.x & 31;
    if (w >= E) return;
    int src = ei[w];
    int dst = ei[E + w];
    const float2* xs = (const float2*)(x + (size_t)src * (D2 * 2));
    float* ad = agg + (size_t)dst * (D2 * 2);
    for (int d = lane; d < D2; d += 32) {
        float2 v = xs[d];
        atomicAdd(ad + 2 * d,     v.x);
        atomicAdd(ad + 2 * d + 1, v.y);
    }
}

// ---------------------------------------------------------------------------
// Fused SAGE GEMM: out = [relu](A0@W0^T [+ A1@W1^T] [+ bias])
//   A : [N, Din] row-major.  W : [Dout, Din] row-major.
// 128x128x8 tile, 256 threads, 8x8 register tile per thread.
#define BM 128
#define BN 128
#define BK 8

// Load 4 k-values starting at even kk from a row whose stride Din is even.
// Always 8-byte aligned -> float2 loads are safe for any even Din.
__device__ __forceinline__ float4 load4_even(const float* __restrict__ base,
                                             int kk, int Din) {
    float4 v = make_float4(0.f, 0.f, 0.f, 0.f);
    if (kk + 3 < Din) {
        float2 p0 = *(const float2*)(base + kk);
        float2 p1 = *(const float2*)(base + kk + 2);
        v.x = p0.x; v.y = p0.y; v.z = p1.x; v.w = p1.y;
    } else if (kk + 1 < Din) {        // Din even: pairs are all-or-nothing
        float2 p0 = *(const float2*)(base + kk);
        v.x = p0.x; v.y = p0.y;
        if (kk + 3 == Din) {          // one more pair? no: kk+2,kk+3 valid iff kk+3<Din
        }
        if (kk + 2 < Din) {           // possible when Din - kk == 3? no (even) — dead
            v.z = base[kk + 2];
        }
    }
    return v;
}

__global__ __launch_bounds__(256)
void sage_gemm(const float* __restrict__ A0,
               const float* __restrict__ A1,
               const float* __restrict__ W0,
               const float* __restrict__ W1,
               const float* __restrict__ bias,
               float* __restrict__ out,
               int N, int Din, int Dout,
               int dual, int doRelu) {
    __shared__ float As[BK][BM];
    __shared__ float Ws[BK][BN];

    int tid = threadIdx.x;                 // 0..255
    int tr = tid >> 4;                     // 0..15 -> rows tr*8..+7
    int tc = tid & 15;                     // 0..15 -> cols tc*8..+7
    int rowBase = blockIdx.y * BM;
    int colBase = blockIdx.x * BN;

    // Tile-loader indices: thread i loads 4 k-values of A and 4 of W.
    int ldRow = tid >> 1;                  // 0..127
    int ldK   = (tid & 1) * 4;             // 0 or 4

    float acc[8][8];
    #pragma unroll
    for (int i = 0; i < 8; ++i)
        #pragma unroll
        for (int j = 0; j < 8; ++j) acc[i][j] = 0.0f;

    int nPhases = dual ? 2 : 1;
    for (int ph = 0; ph < nPhases; ++ph) {
        const float* A = ph ? A1 : A0;
        const float* W = ph ? W1 : W0;
        for (int k0 = 0; k0 < Din; k0 += BK) {
            // ---- Load A tile (128 rows x 8 k).
            {
                int row = rowBase + ldRow;
                int kk = k0 + ldK;
                float4 v = make_float4(0.f, 0.f, 0.f, 0.f);
                if (row < N)
                    v = load4_even(&A[(size_t)row * Din], kk, Din);
                As[ldK    ][ldRow] = v.x;
                As[ldK + 1][ldRow] = v.y;
                As[ldK + 2][ldRow] = v.z;
                As[ldK + 3][ldRow] = v.w;
            }
            // ---- Load W tile (128 cols x 8 k).
            {
                int col = colBase + ldRow;
                int kk = k0 + ldK;
                float4 v = make_float4(0.f, 0.f, 0.f, 0.f);
                if (col < Dout)
                    v = load4_even(&W[(size_t)col * Din], kk, Din);
                Ws[ldK    ][ldRow] = v.x;
                Ws[ldK + 1][ldRow] = v.y;
                Ws[ldK + 2][ldRow] = v.z;
                Ws[ldK + 3][ldRow] = v.w;
            }
            __syncthreads();

            #pragma unroll
            for (int k = 0; k < BK; ++k) {
                float4 a0 = *(const float4*)&As[k][tr * 8];
                float4 a1 = *(const float4*)&As[k][tr * 8 + 4];
                float4 b0 = *(const float4*)&Ws[k][tc * 8];
                float4 b1 = *(const float4*)&Ws[k][tc * 8 + 4];
                float a[8] = {a0.x, a0.y, a0.z, a0.w, a1.x, a1.y, a1.z, a1.w};
                float b[8] = {b0.x, b0.y, b0.z, b0.w, b1.x, b1.y, b1.z, b1.w};
                #pragma unroll
                for (int i = 0; i < 8; ++i)
                    #pragma unroll
                    for (int j = 0; j < 8; ++j)
                        acc[i][j] += a[i] * b[j];
            }
            __syncthreads();
        }
    }

    // Epilogue: float4 stores; Dout is always a multiple of 4.
    #pragma unroll
    for (int jh = 0; jh < 2; ++jh) {
        int col = colBase + tc * 8 + jh * 4;
        if (col >= Dout) continue;
        float4 bv = make_float4(0.f, 0.f, 0.f, 0.f);
        if (bias) bv = *(const float4*)&bias[col];
        #pragma unroll
        for (int i = 0; i < 8; ++i) {
            int row = rowBase + tr * 8 + i;
            if (row >= N) continue;
            float4 v;
            v.x = acc[i][jh * 4 + 0] + bv.x;
            v.y = acc[i][jh * 4 + 1] + bv.y;
            v.z = acc[i][jh * 4 + 2] + bv.z;
            v.w = acc[i][jh * 4 + 3] + bv.w;
            if (doRelu) {
                v.x = v.x > 0.f ? v.x : 0.f;
                v.y = v.y > 0.f ? v.y : 0.f;
                v.z = v.z > 0.f ? v.z : 0.f;
                v.w = v.w > 0.f ? v.w : 0.f;
            }
            *(float4*)&out[(size_t)row * Dout + col] = v;
        }
    }
}

// ---------------------------------------------------------------------------
// Layer-3 finish: per node v = relu(aggU + R + bias); pooled-sum + count.
__global__ void l3_finish(const float* __restrict__ aggU,
                          const float* __restrict__ R,
                          const float* __restrict__ bias,
                          const int* __restrict__ batch,
                          int N, float* __restrict__ out, int colOff,
                          int* __restrict__ cnt) {
    int w = (blockIdx.x * blockDim.x + threadIdx.x) >> 5;
    int lane = threadIdx.x & 31;
    if (w >= N) return;
    int g = batch[w];
    const float* au = aggU + (size_t)w * 128;
    const float* rr = R + (size_t)w * 128;
    float* o = out + (size_t)g * 256 + colOff;
    #pragma unroll
    for (int c = lane; c < 128; c += 32) {
        float v = au[c] + rr[c] + bias[c];
        if (v < 0.0f) v = 0.0f;
        atomicAdd(o + c, v);
    }
    if (lane == 0) atomicAdd(cnt + g, 1);
}

// Divide pooled sums by counts.
__global__ void pool_div(float* __restrict__ out, const int* __restrict__ cnt) {
    int i = blockIdx.x * blockDim.x + threadIdx.x;
    if (i >= GRAPHS * 256) return;
    int g = i >> 8;
    int c = i & 255;
    int n = (c < 128) ? cnt[g] : cnt[GRAPHS + g];
    out[i] /= (float)(n > 0 ? n : 1);
}

// ---------------------------------------------------------------------------
static void run_stack(const float* x0, const int* ei, int E,
                      const int* batch, int N,
                      const float* const* Wp,   // wl1,bl1,wr1,wl2,bl2,wr2,wl3,bl3,wr3
                      int d0, int d1, int d2,   // d3 = 128
                      float* bufA, float* bufB, float* agg,
                      float* out, int colOff, int* cnt) {
    int sc_blocks = (int)(((long long)E * 32 + 255) / 256);
    int gy = (N + BM - 1) / BM;

    // Layer 1: agg = scatter(x0); h1 = relu(dualGEMM) -> bufA
    cudaMemsetAsync(agg, 0, (size_t)N * d0 * sizeof(float));
    scatter_add<<<sc_blocks, 256>>>(x0, ei, E, d0 / 2, agg);
    sage_gemm<<<dim3((d1 + BN - 1) / BN, gy), 256>>>(
        agg, x0, Wp[0], Wp[2], Wp[1], bufA, N, d0, d1, 1, 1);

    // Layer 2: agg = scatter(h1); h2 = relu(dualGEMM) -> bufB
    cudaMemsetAsync(agg, 0, (size_t)N * d1 * sizeof(float));
    scatter_add<<<sc_blocks, 256>>>(bufA, ei, E, d1 / 2, agg);
    sage_gemm<<<dim3((d2 + BN - 1) / BN, gy), 256>>>(
        agg, bufA, Wp[3], Wp[5], Wp[4], bufB, N, d1, d2, 1, 1);

    // Layer 3 (transform-first): U = h2@Wl^T, R = h2@Wr^T, scatter U at D=128.
    float* U = bufA;
    float* R = bufA + (SCRATCH_ELEMS / 2);
    sage_gemm<<<dim3(1, gy), 256>>>(
        bufB, nullptr, Wp[6], nullptr, nullptr, U, N, d2, 128, 0, 0);
    sage_gemm<<<dim3(1, gy), 256>>>(
        bufB, nullptr, Wp[8], nullptr, nullptr, R, N, d2, 128, 0, 0);
    cudaMemsetAsync(agg, 0, (size_t)N * 128 * sizeof(float));
    scatter_add<<<sc_blocks, 256>>>(U, ei, E, 64, agg);
    l3_finish<<<(int)(((long long)N * 32 + 255) / 256), 256>>>(
        agg, R, Wp[7], batch, N, out, colOff, cnt);
}

extern "C" void kernel_launch(void* const* d_in, const int* in_sizes, int n_in,
                              void* d_out, int out_size) {
    const float* x      = (const float*)d_in[0];
    const int*   ei     = (const int*)d_in[1];
    const int*   batch  = (const int*)d_in[2];
    const float* xc     = (const float*)d_in[3];
    const int*   eic    = (const int*)d_in[4];
    const int*   batchc = (const int*)d_in[5];
    const float* W[18];
    for (int i = 0; i < 18; ++i) W[i] = (const float*)d_in[6 + i];
    float* out = (float*)d_out;

    int Nm = in_sizes[2];          // 200000
    int Em = in_sizes[1] / 2;      // 1000000
    int Nc = in_sizes[5];          // 120000
    int Ec = in_sizes[4] / 2;      // 500000

    float *bufA, *bufB, *agg;
    int* cnt;
    cudaGetSymbolAddress((void**)&bufA, g_bufA);
    cudaGetSymbolAddress((void**)&bufB, g_bufB);
    cudaGetSymbolAddress((void**)&agg,  g_agg);
    cudaGetSymbolAddress((void**)&cnt,  g_cnt);

    cudaMemsetAsync(out, 0, (size_t)GRAPHS * 256 * sizeof(float));
    cudaMemsetAsync(cnt, 0, 2 * GRAPHS * sizeof(int));

    // Molecular stack -> out cols [0,128)
    run_stack(x, ei, Em, batch, Nm, W + 0, 78, 156, 312,
              bufA, bufB, agg, out, 0, cnt);

    // Clique stack -> out cols [128,256)
    run_stack(xc, eic, Ec, batchc, Nc, W + 9, 92, 184, 368,
              bufA, bufB, agg, out, 128, cnt + GRAPHS);

    // Mean
    pool_div<<<(GRAPHS * 256 + 255) / 256, 256>>>(out, cnt);
}